// round 2
// baseline (speedup 1.0000x reference)
#include <cuda_runtime.h>

#define N_AG 512
#define T_STEPS 12

// ------------------------- scratch (device globals) -------------------------
__device__ float  g_h[N_AG * 8];
__device__ float  g_cl[N_AG * 8];
__device__ float  g_ctx[N_AG * 8];
__device__ float  g_pos[N_AG * 2];
__device__ float  g_prev[N_AG * 2];
__device__ float  g_A[N_AG * 64];     // A[i][d], row-major
__device__ float2 g_B2[32 * N_AG];    // B pair-transposed: [d/2][j] -> (B[j][2dd], B[j][2dd+1])
__device__ float  g_Mse[128];         // Mse[r][d] = (W_se @ W1[0:32])[r][d], r in {0,1}
__device__ float  g_bias1[64];        // b1 + b_se @ W1[0:32]

// ------------------------- helpers -------------------------
__device__ __forceinline__ float sigf(float x) { return 1.f / (1.f + __expf(-x)); }

__device__ __forceinline__ unsigned long long add2(unsigned long long a, unsigned long long b) {
    unsigned long long r;
    asm("add.rn.f32x2 %0, %1, %2;" : "=l"(r) : "l"(a), "l"(b));
    return r;
}
__device__ __forceinline__ void fma2(unsigned long long& d, unsigned long long a, unsigned long long b) {
    asm("fma.rn.f32x2 %0, %1, %2, %0;" : "+l"(d) : "l"(a), "l"(b));
}
__device__ __forceinline__ void unpack2(unsigned long long v, float& lo, float& hi) {
    asm("mov.b64 {%0, %1}, %2;" : "=f"(lo), "=f"(hi) : "l"(v));
}
__device__ __forceinline__ unsigned long long pack2f(float lo, float hi) {
    unsigned long long r;
    asm("mov.b64 %0, {%1, %2};" : "=l"(r) : "f"(lo), "f"(hi));
    return r;
}
__device__ __forceinline__ unsigned long long relu2(unsigned long long t) {
    float lo, hi;
    unpack2(t, lo, hi);
    lo = fmaxf(lo, 0.f);
    hi = fmaxf(hi, 0.f);
    return pack2f(lo, hi);
}
__device__ __forceinline__ void fma4(float4& a, float s, float4 w) {
    a.x += s * w.x; a.y += s * w.y; a.z += s * w.z; a.w += s * w.w;
}

// ------------------------- init: state + fused layer-1 constants -------------------------
__global__ __launch_bounds__(256) void k_init(
    const float* __restrict__ p, const float* __restrict__ z,
    const float* __restrict__ obs, const float* __restrict__ c0,
    const float* __restrict__ W_zh, const float* __restrict__ b_zh,
    const float* __restrict__ W_se, const float* __restrict__ b_se,
    const float* __restrict__ W1, const float* __restrict__ b1)
{
    int i = blockIdx.x * 256 + threadIdx.x;
    float z0 = z[2 * i], z1 = z[2 * i + 1];
#pragma unroll
    for (int u = 0; u < 8; u++) {
        g_h[i * 8 + u]   = z0 * W_zh[u] + z1 * W_zh[8 + u] + b_zh[u];
        g_cl[i * 8 + u]  = c0[i * 8 + u];
        g_ctx[i * 8 + u] = 0.f;
    }
    g_pos[2 * i]     = obs[(7 * N_AG + i) * 2];
    g_pos[2 * i + 1] = obs[(7 * N_AG + i) * 2 + 1];
    g_prev[2 * i]     = p[2 * i];
    g_prev[2 * i + 1] = p[2 * i + 1];

    if (blockIdx.x == 0 && threadIdx.x < 64) {
        int d = threadIdx.x;
        float m0 = 0.f, m1 = 0.f, bb = b1[d];
        for (int u = 0; u < 32; u++) {
            float w = W1[u * 64 + d];
            m0 += W_se[u] * w;        // W_se[0][u]
            m1 += W_se[32 + u] * w;   // W_se[1][u]
            bb += b_se[u] * w;
        }
        g_Mse[d]      = m0;
        g_Mse[64 + d] = m1;
        g_bias1[d]    = bb;
    }
}

// ------------------------- fused per-step small kernel -------------------------
// Does: epilogue of step (t-1): mu/logvar/position/outputs + pos/prev update,
// then (if t < 12) LSTM of step t + A/B vector precompute for pooling.
__global__ __launch_bounds__(128) void k_small(
    int t,
    const float* __restrict__ c, const float* __restrict__ z, const float* __restrict__ eps,
    const float* __restrict__ W_in, const float* __restrict__ b_in,
    const float* __restrict__ W_ih, const float* __restrict__ W_hh,
    const float* __restrict__ b_ih, const float* __restrict__ b_hh,
    const float* __restrict__ W1,
    const float* __restrict__ W_m, const float* __restrict__ b_m,
    const float* __restrict__ W_v, const float* __restrict__ b_v,
    float* __restrict__ out)
{
    int i = blockIdx.x * 128 + threadIdx.x;

    float h[8], cl[8], ctx[8];
#pragma unroll
    for (int u = 0; u < 8; u++) {
        h[u]   = g_h[i * 8 + u];
        cl[u]  = g_cl[i * 8 + u];
        ctx[u] = g_ctx[i * 8 + u];
    }

    float pos0, pos1, pv0, pv1;
    if (t > 0) {
        int tc = t - 1;
        float mu[2], lv[2];
#pragma unroll
        for (int m = 0; m < 2; m++) {
            float s  = b_m[m];
            float s2 = b_v[m];
#pragma unroll
            for (int u = 0; u < 4; u++) {
                s  += h[u]     * W_m[u * 2 + m];
                s2 += h[4 + u] * W_v[u * 2 + m];
            }
#pragma unroll
            for (int k = 0; k < 8; k++) {
                s  += ctx[k] * W_m[(4 + k) * 2 + m];
                s2 += ctx[k] * W_v[(4 + k) * 2 + m];
            }
            mu[m] = s; lv[m] = s2;
        }
        float e0 = eps[(tc * N_AG + i) * 2];
        float e1 = eps[(tc * N_AG + i) * 2 + 1];
        float p0 = mu[0] + e0 * expf(0.5f * lv[0]);
        float p1 = mu[1] + e1 * expf(0.5f * lv[1]);
        // outputs: positions | means | logvars, each (12, 512, 2)
        out[tc * 1024 + 2 * i]             = p0;
        out[tc * 1024 + 2 * i + 1]         = p1;
        out[12288 + tc * 1024 + 2 * i]     = mu[0];
        out[12288 + tc * 1024 + 2 * i + 1] = mu[1];
        out[24576 + tc * 1024 + 2 * i]     = lv[0];
        out[24576 + tc * 1024 + 2 * i + 1] = lv[1];
        pv0 = p0; pv1 = p1;
        pos0 = g_pos[2 * i] + p0;
        pos1 = g_pos[2 * i + 1] + p1;
        g_prev[2 * i] = pv0; g_prev[2 * i + 1] = pv1;
        g_pos[2 * i] = pos0; g_pos[2 * i + 1] = pos1;
    } else {
        pv0 = g_prev[2 * i]; pv1 = g_prev[2 * i + 1];
        pos0 = g_pos[2 * i]; pos1 = g_pos[2 * i + 1];
    }

    if (t >= T_STEPS) return;

    // x = [ctx(8), prev(2), c(8), z(2)]
    float x[20];
#pragma unroll
    for (int u = 0; u < 8; u++) x[u] = ctx[u];
    x[8] = pv0; x[9] = pv1;
#pragma unroll
    for (int u = 0; u < 8; u++) x[10 + u] = c[i * 8 + u];
    x[18] = z[2 * i]; x[19] = z[2 * i + 1];

    // xr = relu(x @ W_in + b_in), W_in (20,16)
    const float4* Win4 = (const float4*)W_in;
    const float4* bin4 = (const float4*)b_in;
    float4 xa[4];
#pragma unroll
    for (int q = 0; q < 4; q++) xa[q] = bin4[q];
#pragma unroll
    for (int v = 0; v < 20; v++) {
        float s = x[v];
#pragma unroll
        for (int q = 0; q < 4; q++) fma4(xa[q], s, Win4[v * 4 + q]);
    }
    float xr[16];
    float* xas = (float*)xa;
#pragma unroll
    for (int u = 0; u < 16; u++) xr[u] = fmaxf(xas[u], 0.f);

    // gates = xr @ W_ih + h @ W_hh + b_ih + b_hh  (16,32) (8,32)
    const float4* Wih4 = (const float4*)W_ih;
    const float4* Whh4 = (const float4*)W_hh;
    const float4* bih4 = (const float4*)b_ih;
    const float4* bhh4 = (const float4*)b_hh;
    float4 ga[8];
#pragma unroll
    for (int q = 0; q < 8; q++) {
        float4 a = bih4[q], b = bhh4[q];
        ga[q] = make_float4(a.x + b.x, a.y + b.y, a.z + b.z, a.w + b.w);
    }
#pragma unroll
    for (int u = 0; u < 16; u++) {
        float s = xr[u];
#pragma unroll
        for (int q = 0; q < 8; q++) fma4(ga[q], s, Wih4[u * 8 + q]);
    }
#pragma unroll
    for (int u = 0; u < 8; u++) {
        float s = h[u];
#pragma unroll
        for (int q = 0; q < 8; q++) fma4(ga[q], s, Whh4[u * 8 + q]);
    }
    float* gs = (float*)ga;   // gates[32], order i,f,g,o
#pragma unroll
    for (int u = 0; u < 8; u++) {
        float ig = sigf(gs[u]);
        float fg = sigf(gs[8 + u]);
        float gg = tanhf(gs[16 + u]);
        float og = sigf(gs[24 + u]);
        cl[u] = fg * cl[u] + ig * gg;
        h[u]  = og * tanhf(cl[u]);
    }
#pragma unroll
    for (int u = 0; u < 8; u++) {
        g_h[i * 8 + u]  = h[u];
        g_cl[i * 8 + u] = cl[u];
    }

    // A[i][d] = bias1[d] + pos@Mse[:,d] + sum_u h[u]*W1[40+u][d]
    // B[i][d] = -pos@Mse[:,d]           + sum_u h[u]*W1[32+u][d]
    const float4* W1_4   = (const float4*)W1;
    const float4* Mse4   = (const float4*)g_Mse;
    const float4* bias14 = (const float4*)g_bias1;
    float4 a4[16], b4[16];
#pragma unroll
    for (int q = 0; q < 16; q++) {
        float4 base = make_float4(0.f, 0.f, 0.f, 0.f);
        fma4(base, pos0, Mse4[q]);
        fma4(base, pos1, Mse4[16 + q]);
        float4 bb = bias14[q];
        a4[q] = make_float4(bb.x + base.x, bb.y + base.y, bb.z + base.z, bb.w + base.w);
        b4[q] = make_float4(-base.x, -base.y, -base.z, -base.w);
    }
#pragma unroll
    for (int u = 0; u < 8; u++) {
        float s = h[u];
#pragma unroll
        for (int q = 0; q < 16; q++) {
            fma4(a4[q], s, W1_4[(40 + u) * 16 + q]);
            fma4(b4[q], s, W1_4[(32 + u) * 16 + q]);
        }
    }
    float4* gA4 = (float4*)g_A;
#pragma unroll
    for (int q = 0; q < 16; q++) gA4[i * 16 + q] = a4[q];
    float* bs = (float*)b4;
#pragma unroll
    for (int d2 = 0; d2 < 32; d2++)
        g_B2[d2 * N_AG + i] = make_float2(bs[2 * d2], bs[2 * d2 + 1]);
}

// ------------------------- pooling kernel (the N^2 part) -------------------------
// warp per i (2 warps/block, grid 256). Lane handles 2 j's per pass (j and j+32).
// Inner product over d done with packed f32x2 FMA (2 FMAs/issue slot).
__global__ __launch_bounds__(64) void k_pool(
    int t, const int* __restrict__ nei,
    const float* __restrict__ W2, const float* __restrict__ b2)
{
    __shared__ float2 A2sh[2][32];
    __shared__ ulonglong2 w2p[32][4];   // [d-pair][k-pair]: .x -> k=2kk, .y -> k=2kk+1

    int tid = threadIdx.x;
    for (int e = tid; e < 128; e += 64) {
        int dd = e >> 2, kk = e & 3;
        ulonglong2 v;
        v.x = pack2f(W2[(2 * dd) * 8 + 2 * kk],     W2[(2 * dd + 1) * 8 + 2 * kk]);
        v.y = pack2f(W2[(2 * dd) * 8 + 2 * kk + 1], W2[(2 * dd + 1) * 8 + 2 * kk + 1]);
        w2p[dd][kk] = v;
    }
    {
        int iw = tid >> 5, d2 = tid & 31;
        A2sh[iw][d2] = ((const float2*)g_A)[(blockIdx.x * 2 + iw) * 32 + d2];
    }
    __syncthreads();

    int lane = tid & 31;
    int warp = tid >> 5;
    int i = blockIdx.x * 2 + warp;

    float b2r[8];
#pragma unroll
    for (int k = 0; k < 8; k++) b2r[k] = b2[k];

    float m[8];
#pragma unroll
    for (int k = 0; k < 8; k++) m[k] = 0.f;   // ph >= 0 and -inf->0 semantics => 0 init

    const int* neirow = nei + (t * N_AG + i) * N_AG;
    const unsigned long long* B2   = (const unsigned long long*)g_B2;
    const unsigned long long* Arow = (const unsigned long long*)A2sh[warp];

    for (int jg = 0; jg < 8; jg++) {
        int j0 = jg * 64 + lane;
        int j1 = j0 + 32;
        int n0 = neirow[j0];
        int n1 = neirow[j1];

        unsigned long long acc0[8], acc1[8];
#pragma unroll
        for (int k = 0; k < 8; k++) { acc0[k] = 0ULL; acc1[k] = 0ULL; }

#pragma unroll
        for (int dd = 0; dd < 32; dd++) {
            unsigned long long a2 = Arow[dd];
            unsigned long long t0 = relu2(add2(a2, B2[dd * N_AG + j0]));
            unsigned long long t1 = relu2(add2(a2, B2[dd * N_AG + j1]));
#pragma unroll
            for (int kk = 0; kk < 4; kk++) {
                ulonglong2 w = w2p[dd][kk];
                fma2(acc0[2 * kk],     t0, w.x);
                fma2(acc0[2 * kk + 1], t0, w.y);
                fma2(acc1[2 * kk],     t1, w.x);
                fma2(acc1[2 * kk + 1], t1, w.y);
            }
        }
#pragma unroll
        for (int k = 0; k < 8; k++) {
            float lo, hi;
            unpack2(acc0[k], lo, hi);
            float s0 = fmaxf(lo + hi + b2r[k], 0.f);
            unpack2(acc1[k], lo, hi);
            float s1 = fmaxf(lo + hi + b2r[k], 0.f);
            if (n0 > 0) m[k] = fmaxf(m[k], s0);
            if (n1 > 0) m[k] = fmaxf(m[k], s1);
        }
    }

#pragma unroll
    for (int k = 0; k < 8; k++) {
        m[k] = fmaxf(m[k], __shfl_xor_sync(0xffffffffu, m[k], 16));
        m[k] = fmaxf(m[k], __shfl_xor_sync(0xffffffffu, m[k], 8));
        m[k] = fmaxf(m[k], __shfl_xor_sync(0xffffffffu, m[k], 4));
        m[k] = fmaxf(m[k], __shfl_xor_sync(0xffffffffu, m[k], 2));
        m[k] = fmaxf(m[k], __shfl_xor_sync(0xffffffffu, m[k], 1));
    }
    if (lane < 8) g_ctx[i * 8 + lane] = m[lane];
}

// ------------------------- launch -------------------------
extern "C" void kernel_launch(void* const* d_in, const int* in_sizes, int n_in,
                              void* d_out, int out_size)
{
    const float* p    = (const float*)d_in[0];
    const float* c    = (const float*)d_in[1];
    const float* z    = (const float*)d_in[2];
    const float* obs  = (const float*)d_in[3];
    const float* eps  = (const float*)d_in[4];
    const float* c0   = (const float*)d_in[5];
    const int*   nei  = (const int*)d_in[6];
    // d_in[7] = nei_num_index (unused by reference)
    const float* W_in = (const float*)d_in[8];
    const float* b_in = (const float*)d_in[9];
    const float* W_ih = (const float*)d_in[10];
    const float* W_hh = (const float*)d_in[11];
    const float* b_ih = (const float*)d_in[12];
    const float* b_hh = (const float*)d_in[13];
    const float* W_m  = (const float*)d_in[14];
    const float* b_m  = (const float*)d_in[15];
    const float* W_v  = (const float*)d_in[16];
    const float* b_v  = (const float*)d_in[17];
    const float* W_zh = (const float*)d_in[18];
    const float* b_zh = (const float*)d_in[19];
    const float* W_se = (const float*)d_in[20];
    const float* b_se = (const float*)d_in[21];
    const float* W1   = (const float*)d_in[22];
    const float* b1   = (const float*)d_in[23];
    const float* W2   = (const float*)d_in[24];
    const float* b2   = (const float*)d_in[25];
    float* out = (float*)d_out;

    k_init<<<2, 256>>>(p, z, obs, c0, W_zh, b_zh, W_se, b_se, W1, b1);
    for (int t = 0; t < T_STEPS; t++) {
        k_small<<<4, 128>>>(t, c, z, eps, W_in, b_in, W_ih, W_hh, b_ih, b_hh,
                            W1, W_m, b_m, W_v, b_v, out);
        k_pool<<<256, 64>>>(t, nei, W2, b2);
    }
    k_small<<<4, 128>>>(T_STEPS, c, z, eps, W_in, b_in, W_ih, W_hh, b_ih, b_hh,
                        W1, W_m, b_m, W_v, b_v, out);
}

// round 3
// speedup vs baseline: 1.2703x; 1.2703x over previous
#include <cuda_runtime.h>

#define N_AG 512
#define T_STEPS 12
typedef unsigned long long ull;

// ------------------------- scratch (device globals) -------------------------
__device__ float  g_h[N_AG * 8];
__device__ float  g_cl[N_AG * 8];
__device__ float  g_ctx[N_AG * 8];
__device__ float  g_pos[N_AG * 2];
__device__ float  g_prev[N_AG * 2];
__device__ float  g_A[N_AG * 64];     // A[i][d], row-major
__device__ float2 g_B2[32 * N_AG];    // B pair-transposed: [d/2][j]
__device__ float  g_Mse[128];         // (W_se @ W1[0:32]) rows 0,1
__device__ float  g_bias1[64];        // b1 + b_se @ W1[0:32]

// ------------------------- helpers -------------------------
__device__ __forceinline__ float sigf(float x) { return 1.f / (1.f + __expf(-x)); }

__device__ __forceinline__ ull add2(ull a, ull b) {
    ull r; asm("add.rn.f32x2 %0, %1, %2;" : "=l"(r) : "l"(a), "l"(b)); return r;
}
__device__ __forceinline__ void fma2(ull& d, ull a, ull b) {
    asm("fma.rn.f32x2 %0, %1, %2, %0;" : "+l"(d) : "l"(a), "l"(b));
}
__device__ __forceinline__ void unpack2(ull v, float& lo, float& hi) {
    asm("mov.b64 {%0, %1}, %2;" : "=f"(lo), "=f"(hi) : "l"(v));
}
__device__ __forceinline__ ull pack2f(float lo, float hi) {
    ull r; asm("mov.b64 %0, {%1, %2};" : "=l"(r) : "f"(lo), "f"(hi)); return r;
}
__device__ __forceinline__ ull relu2(ull t) {
    float lo, hi; unpack2(t, lo, hi);
    return pack2f(fmaxf(lo, 0.f), fmaxf(hi, 0.f));
}

// ------------------------- init -------------------------
__global__ __launch_bounds__(256) void k_init(
    const float* __restrict__ p, const float* __restrict__ z,
    const float* __restrict__ obs, const float* __restrict__ c0,
    const float* __restrict__ W_zh, const float* __restrict__ b_zh,
    const float* __restrict__ W_se, const float* __restrict__ b_se,
    const float* __restrict__ W1, const float* __restrict__ b1)
{
    int i = blockIdx.x * 256 + threadIdx.x;
    float z0 = z[2 * i], z1 = z[2 * i + 1];
#pragma unroll
    for (int u = 0; u < 8; u++) {
        g_h[i * 8 + u]   = z0 * W_zh[u] + z1 * W_zh[8 + u] + b_zh[u];
        g_cl[i * 8 + u]  = c0[i * 8 + u];
        g_ctx[i * 8 + u] = 0.f;
    }
    g_pos[2 * i]      = obs[(7 * N_AG + i) * 2];
    g_pos[2 * i + 1]  = obs[(7 * N_AG + i) * 2 + 1];
    g_prev[2 * i]     = p[2 * i];
    g_prev[2 * i + 1] = p[2 * i + 1];

    if (blockIdx.x == 0 && threadIdx.x < 64) {
        int d = threadIdx.x;
        float m0 = 0.f, m1 = 0.f, bb = b1[d];
        for (int u = 0; u < 32; u++) {
            float w = W1[u * 64 + d];
            m0 += W_se[u] * w;
            m1 += W_se[32 + u] * w;
            bb += b_se[u] * w;
        }
        g_Mse[d]      = m0;
        g_Mse[64 + d] = m1;
        g_bias1[d]    = bb;
    }
}

// ------------------------- fused per-step kernel: warp per agent -------------------------
// epilogue of step t-1 (mu/logvar/position + pos update), then LSTM of step t,
// then A/B precompute for pooling. 512 warps chip-wide.
__global__ __launch_bounds__(256) void k_step(
    int t,
    const float* __restrict__ c, const float* __restrict__ z, const float* __restrict__ eps,
    const float* __restrict__ W_in, const float* __restrict__ b_in,
    const float* __restrict__ W_ih, const float* __restrict__ W_hh,
    const float* __restrict__ b_ih, const float* __restrict__ b_hh,
    const float* __restrict__ W1,
    const float* __restrict__ W_m, const float* __restrict__ b_m,
    const float* __restrict__ W_v, const float* __restrict__ b_v,
    float* __restrict__ out)
{
    int warp = threadIdx.x >> 5;
    int lane = threadIdx.x & 31;
    int i = blockIdx.x * 8 + warp;

    float h[8], cl8, ctx[8];
#pragma unroll
    for (int u = 0; u < 8; u++) {
        h[u]   = g_h[i * 8 + u];
        ctx[u] = g_ctx[i * 8 + u];
    }
    cl8 = g_cl[i * 8 + (lane & 7)];    // lane u holds cl[u] (lanes 8+ duplicate)

    float pos0, pos1, pv0, pv1;
    if (t > 0) {
        int tc = t - 1;
        float mu[2], lv[2];
#pragma unroll
        for (int m = 0; m < 2; m++) {
            float s  = b_m[m];
            float s2 = b_v[m];
#pragma unroll
            for (int u = 0; u < 4; u++) {
                s  += h[u]     * W_m[u * 2 + m];
                s2 += h[4 + u] * W_v[u * 2 + m];
            }
#pragma unroll
            for (int k = 0; k < 8; k++) {
                s  += ctx[k] * W_m[(4 + k) * 2 + m];
                s2 += ctx[k] * W_v[(4 + k) * 2 + m];
            }
            mu[m] = s; lv[m] = s2;
        }
        float e0 = eps[(tc * N_AG + i) * 2];
        float e1 = eps[(tc * N_AG + i) * 2 + 1];
        float p0 = mu[0] + e0 * expf(0.5f * lv[0]);
        float p1 = mu[1] + e1 * expf(0.5f * lv[1]);
        pv0 = p0; pv1 = p1;
        pos0 = g_pos[2 * i] + p0;
        pos1 = g_pos[2 * i + 1] + p1;
        if (lane == 0) {
            out[tc * 1024 + 2 * i]             = p0;
            out[tc * 1024 + 2 * i + 1]         = p1;
            out[12288 + tc * 1024 + 2 * i]     = mu[0];
            out[12288 + tc * 1024 + 2 * i + 1] = mu[1];
            out[24576 + tc * 1024 + 2 * i]     = lv[0];
            out[24576 + tc * 1024 + 2 * i + 1] = lv[1];
            g_prev[2 * i] = pv0; g_prev[2 * i + 1] = pv1;
            g_pos[2 * i] = pos0; g_pos[2 * i + 1] = pos1;
        }
    } else {
        pv0 = g_prev[2 * i]; pv1 = g_prev[2 * i + 1];
        pos0 = g_pos[2 * i]; pos1 = g_pos[2 * i + 1];
    }

    if (t >= T_STEPS) return;

    // x = [ctx(8), prev(2), c(8), z(2)]  (all lanes hold full x)
    float x[20];
#pragma unroll
    for (int u = 0; u < 8; u++) x[u] = ctx[u];
    x[8] = pv0; x[9] = pv1;
#pragma unroll
    for (int u = 0; u < 8; u++) x[10 + u] = c[i * 8 + u];
    x[18] = z[2 * i]; x[19] = z[2 * i + 1];

    // relu layer: lane l<16 computes xr[l]
    float xr = 0.f;
    if (lane < 16) {
        float s = b_in[lane];
#pragma unroll
        for (int v = 0; v < 20; v++) s += x[v] * W_in[v * 16 + lane];
        xr = fmaxf(s, 0.f);
    }

    // gates: lane l computes gates[l]
    float g = b_ih[lane] + b_hh[lane];
#pragma unroll
    for (int u = 0; u < 16; u++) {
        float xu = __shfl_sync(0xffffffffu, xr, u);
        g += xu * W_ih[u * 32 + lane];
    }
#pragma unroll
    for (int u = 0; u < 8; u++) g += h[u] * W_hh[u * 32 + lane];

    // nonlinearities: lanes compute cell/h for u = lane&7 (lanes 8+ duplicate)
    int u8 = lane & 7;
    float gi = __shfl_sync(0xffffffffu, g, u8);
    float gf = __shfl_sync(0xffffffffu, g, u8 + 8);
    float gg = __shfl_sync(0xffffffffu, g, u8 + 16);
    float go = __shfl_sync(0xffffffffu, g, u8 + 24);
    float cln = sigf(gf) * cl8 + sigf(gi) * tanhf(gg);
    float hn  = sigf(go) * tanhf(cln);
    if (lane < 8) {
        g_cl[i * 8 + lane] = cln;
        g_h[i * 8 + lane]  = hn;
    }
    float hw[8];
#pragma unroll
    for (int u = 0; u < 8; u++) hw[u] = __shfl_sync(0xffffffffu, hn, u);

    // A/B precompute: lane l owns d-pair (2l, 2l+1)
    int d = 2 * lane;
    float2 m0 = *(const float2*)(g_Mse + d);
    float2 m1 = *(const float2*)(g_Mse + 64 + d);
    float2 bb = *(const float2*)(g_bias1 + d);
    float bx = pos0 * m0.x + pos1 * m1.x;
    float by = pos0 * m0.y + pos1 * m1.y;
    float Ax = bb.x + bx, Ay = bb.y + by;
    float Bx = -bx, By = -by;
#pragma unroll
    for (int u = 0; u < 8; u++) {
        float2 wA = *(const float2*)(W1 + (40 + u) * 64 + d);
        float2 wB = *(const float2*)(W1 + (32 + u) * 64 + d);
        Ax += hw[u] * wA.x; Ay += hw[u] * wA.y;
        Bx += hw[u] * wB.x; By += hw[u] * wB.y;
    }
    ((float2*)g_A)[i * 32 + lane] = make_float2(Ax, Ay);
    g_B2[lane * N_AG + i] = make_float2(Bx, By);
}

// ------------------------- pooling kernel -------------------------
// 256 blocks x 256 threads. Block handles agents i0=2b, i1=2b+1 (4 warps each).
// Each warp covers 128 j's (2 passes of 2 j's per lane). Packed f32x2 FMA inner.
__global__ __launch_bounds__(256) void k_pool(
    int t, const int* __restrict__ nei,
    const float* __restrict__ W2, const float* __restrict__ b2)
{
    __shared__ float2 A2sh[2][32];
    __shared__ ulonglong2 w2p[32][4];
    __shared__ float red[8][8];

    int tid = threadIdx.x;
    if (tid < 128) {
        int dd = tid >> 2, kk = tid & 3;
        ulonglong2 v;
        v.x = pack2f(W2[(2 * dd) * 8 + 2 * kk],     W2[(2 * dd + 1) * 8 + 2 * kk]);
        v.y = pack2f(W2[(2 * dd) * 8 + 2 * kk + 1], W2[(2 * dd + 1) * 8 + 2 * kk + 1]);
        w2p[dd][kk] = v;
    } else if (tid < 192) {
        int e = tid - 128;
        int ig = e >> 5, d2 = e & 31;
        A2sh[ig][d2] = ((const float2*)g_A)[(blockIdx.x * 2 + ig) * 32 + d2];
    }
    __syncthreads();

    int warp = tid >> 5;
    int lane = tid & 31;
    int ig = warp >> 2;     // which agent in this block
    int wq = warp & 3;      // quarter of j-space
    int i = blockIdx.x * 2 + ig;

    float b2r[8];
#pragma unroll
    for (int k = 0; k < 8; k++) b2r[k] = b2[k];

    float m[8];
#pragma unroll
    for (int k = 0; k < 8; k++) m[k] = 0.f;   // ph>=0 and -inf->0 => 0 init

    const int* neirow = nei + (t * N_AG + i) * N_AG;
    const ull* B2   = (const ull*)g_B2;
    const ull* Arow = (const ull*)A2sh[ig];

#pragma unroll
    for (int jg = 0; jg < 2; jg++) {
        int j0 = wq * 128 + jg * 64 + lane;
        int j1 = j0 + 32;
        int n0 = neirow[j0];
        int n1 = neirow[j1];

        ull acc0[8], acc1[8];
#pragma unroll
        for (int k = 0; k < 8; k++) { acc0[k] = 0ULL; acc1[k] = 0ULL; }

#pragma unroll
        for (int dd = 0; dd < 32; dd++) {
            ull a2 = Arow[dd];
            ull t0 = relu2(add2(a2, B2[dd * N_AG + j0]));
            ull t1 = relu2(add2(a2, B2[dd * N_AG + j1]));
#pragma unroll
            for (int kk = 0; kk < 4; kk++) {
                ulonglong2 w = w2p[dd][kk];
                fma2(acc0[2 * kk],     t0, w.x);
                fma2(acc0[2 * kk + 1], t0, w.y);
                fma2(acc1[2 * kk],     t1, w.x);
                fma2(acc1[2 * kk + 1], t1, w.y);
            }
        }
#pragma unroll
        for (int k = 0; k < 8; k++) {
            float lo, hi;
            unpack2(acc0[k], lo, hi);
            float s0 = fmaxf(lo + hi + b2r[k], 0.f);
            unpack2(acc1[k], lo, hi);
            float s1 = fmaxf(lo + hi + b2r[k], 0.f);
            if (n0 > 0) m[k] = fmaxf(m[k], s0);
            if (n1 > 0) m[k] = fmaxf(m[k], s1);
        }
    }

#pragma unroll
    for (int k = 0; k < 8; k++) {
        m[k] = fmaxf(m[k], __shfl_xor_sync(0xffffffffu, m[k], 16));
        m[k] = fmaxf(m[k], __shfl_xor_sync(0xffffffffu, m[k], 8));
        m[k] = fmaxf(m[k], __shfl_xor_sync(0xffffffffu, m[k], 4));
        m[k] = fmaxf(m[k], __shfl_xor_sync(0xffffffffu, m[k], 2));
        m[k] = fmaxf(m[k], __shfl_xor_sync(0xffffffffu, m[k], 1));
    }
    if (lane < 8) red[warp][lane] = m[lane];
    __syncthreads();

    if ((warp == 0 || warp == 4) && lane < 8) {
        float v = fmaxf(fmaxf(red[warp][lane], red[warp + 1][lane]),
                        fmaxf(red[warp + 2][lane], red[warp + 3][lane]));
        g_ctx[i * 8 + lane] = v;
    }
}

// ------------------------- launch -------------------------
extern "C" void kernel_launch(void* const* d_in, const int* in_sizes, int n_in,
                              void* d_out, int out_size)
{
    const float* p    = (const float*)d_in[0];
    const float* c    = (const float*)d_in[1];
    const float* z    = (const float*)d_in[2];
    const float* obs  = (const float*)d_in[3];
    const float* eps  = (const float*)d_in[4];
    const float* c0   = (const float*)d_in[5];
    const int*   nei  = (const int*)d_in[6];
    const float* W_in = (const float*)d_in[8];
    const float* b_in = (const float*)d_in[9];
    const float* W_ih = (const float*)d_in[10];
    const float* W_hh = (const float*)d_in[11];
    const float* b_ih = (const float*)d_in[12];
    const float* b_hh = (const float*)d_in[13];
    const float* W_m  = (const float*)d_in[14];
    const float* b_m  = (const float*)d_in[15];
    const float* W_v  = (const float*)d_in[16];
    const float* b_v  = (const float*)d_in[17];
    const float* W_zh = (const float*)d_in[18];
    const float* b_zh = (const float*)d_in[19];
    const float* W_se = (const float*)d_in[20];
    const float* b_se = (const float*)d_in[21];
    const float* W1   = (const float*)d_in[22];
    const float* b1   = (const float*)d_in[23];
    const float* W2   = (const float*)d_in[24];
    const float* b2   = (const float*)d_in[25];
    float* out = (float*)d_out;

    k_init<<<2, 256>>>(p, z, obs, c0, W_zh, b_zh, W_se, b_se, W1, b1);
    for (int t = 0; t < T_STEPS; t++) {
        k_step<<<64, 256>>>(t, c, z, eps, W_in, b_in, W_ih, W_hh, b_ih, b_hh,
                            W1, W_m, b_m, W_v, b_v, out);
        k_pool<<<256, 256>>>(t, nei, W2, b2);
    }
    k_step<<<64, 256>>>(T_STEPS, c, z, eps, W_in, b_in, W_ih, W_hh, b_ih, b_hh,
                        W1, W_m, b_m, W_v, b_v, out);
}

// round 4
// speedup vs baseline: 6.9442x; 5.4665x over previous
#include <cuda_runtime.h>

#define N_AG 512
#define T_STEPS 12
#define NB 128
#define NT 512

// ------------------------- cross-block scratch -------------------------
__device__ float2 g_B2buf[2][32 * N_AG];       // [buf][dd*512 + j] = (B[j][2dd], B[j][2dd+1])
__device__ unsigned g_cnt[T_STEPS];
__device__ volatile unsigned g_flag[T_STEPS];
__device__ unsigned g_depart;

__device__ __forceinline__ float sigf(float x) { return 1.f / (1.f + __expf(-x)); }

__global__ __launch_bounds__(NT, 1) void k_fused(
    const float* __restrict__ p, const float* __restrict__ c, const float* __restrict__ z,
    const float* __restrict__ obs, const float* __restrict__ eps, const float* __restrict__ c0,
    const int* __restrict__ nei,
    const float* __restrict__ W_in, const float* __restrict__ b_in,
    const float* __restrict__ W_ih, const float* __restrict__ W_hh,
    const float* __restrict__ b_ih, const float* __restrict__ b_hh,
    const float* __restrict__ W_m, const float* __restrict__ b_m,
    const float* __restrict__ W_v, const float* __restrict__ b_v,
    const float* __restrict__ W_zh, const float* __restrict__ b_zh,
    const float* __restrict__ W_se, const float* __restrict__ b_se,
    const float* __restrict__ W1, const float* __restrict__ b1,
    const float* __restrict__ W2, const float* __restrict__ b2,
    float* __restrict__ out)
{
    __shared__ float4 w2a[32][2];      // W2[2dd][4h..4h+3]
    __shared__ float4 w2b[32][2];      // W2[2dd+1][4h..4h+3]
    __shared__ float  sh_Mse0[64];     // (W_se row0 @ W1[0:32])[d]
    __shared__ float  sh_Mse1[64];     // (W_se row1 @ W1[0:32])[d]
    __shared__ float  sh_b1[64];       // b1 + b_se @ W1[0:32]
    __shared__ float  sh_b2[8];
    __shared__ float2 Ash[4][32];      // A[i][d] pairs, per agent
    __shared__ float  sh_h[4][8], sh_cl[4][8], sh_ctx[4][8];
    __shared__ float2 sh_pos[4], sh_prev[4];
    __shared__ float  red[16][8];      // per-warp partial maxes

    const int tid  = threadIdx.x;
    const int warp = tid >> 5;
    const int lane = tid & 31;
    const int blk  = blockIdx.x;

    // ---------------- preload constants ----------------
    if (tid < 64) {
        int d = tid;
        float m0 = 0.f, m1 = 0.f, bb = b1[d];
        for (int u = 0; u < 32; u++) {
            float w = W1[u * 64 + d];
            m0 += W_se[u] * w;
            m1 += W_se[32 + u] * w;
            bb += b_se[u] * w;
        }
        sh_Mse0[d] = m0; sh_Mse1[d] = m1; sh_b1[d] = bb;
    } else if (tid < 192) {
        int e = tid - 64;               // 128 entries: dd(32) x r(2) x h(2)
        int dd = e >> 2, r = (e >> 1) & 1, hh = e & 1;
        const float* row = W2 + (2 * dd + r) * 8 + 4 * hh;
        float4 v = make_float4(row[0], row[1], row[2], row[3]);
        if (r == 0) w2a[dd][hh] = v; else w2b[dd][hh] = v;
    } else if (tid < 200) {
        sh_b2[tid - 192] = b2[tid - 192];
    }

    // ---------------- init per-agent state (warps 0..3) ----------------
    if (warp < 4) {
        int i = blk * 4 + warp;
        if (lane < 8) {
            float z0 = z[2 * i], z1 = z[2 * i + 1];
            sh_h[warp][lane]   = z0 * W_zh[lane] + z1 * W_zh[8 + lane] + b_zh[lane];
            sh_cl[warp][lane]  = c0[i * 8 + lane];
            sh_ctx[warp][lane] = 0.f;
        }
        if (lane == 0) {
            sh_pos[warp]  = make_float2(obs[(7 * N_AG + i) * 2], obs[(7 * N_AG + i) * 2 + 1]);
            sh_prev[warp] = make_float2(p[2 * i], p[2 * i + 1]);
        }
    }
    __syncthreads();

    for (int t = 0; t <= T_STEPS; t++) {
        // ================= step phase (warps 0..3, one agent each) =================
        if (warp < 4) {
            int a = warp;
            int i = blk * 4 + a;

            if (t >= 1 && lane < 8) {
                float v = fmaxf(fmaxf(red[a * 4 + 0][lane], red[a * 4 + 1][lane]),
                                fmaxf(red[a * 4 + 2][lane], red[a * 4 + 3][lane]));
                sh_ctx[a][lane] = v;
            }
            __syncwarp();

            float h[8], ctx[8];
#pragma unroll
            for (int u = 0; u < 8; u++) { h[u] = sh_h[a][u]; ctx[u] = sh_ctx[a][u]; }
            float cl8 = sh_cl[a][lane & 7];

            float pos0, pos1, pv0, pv1;
            if (t > 0) {
                int tc = t - 1;
                float mu[2], lv[2];
#pragma unroll
                for (int m = 0; m < 2; m++) {
                    float s  = b_m[m];
                    float s2 = b_v[m];
#pragma unroll
                    for (int u = 0; u < 4; u++) {
                        s  += h[u]     * W_m[u * 2 + m];
                        s2 += h[4 + u] * W_v[u * 2 + m];
                    }
#pragma unroll
                    for (int k = 0; k < 8; k++) {
                        s  += ctx[k] * W_m[(4 + k) * 2 + m];
                        s2 += ctx[k] * W_v[(4 + k) * 2 + m];
                    }
                    mu[m] = s; lv[m] = s2;
                }
                float e0 = eps[(tc * N_AG + i) * 2];
                float e1 = eps[(tc * N_AG + i) * 2 + 1];
                float p0 = mu[0] + e0 * expf(0.5f * lv[0]);
                float p1 = mu[1] + e1 * expf(0.5f * lv[1]);
                pv0 = p0; pv1 = p1;
                pos0 = sh_pos[a].x + p0;
                pos1 = sh_pos[a].y + p1;
                if (lane == 0) {
                    out[tc * 1024 + 2 * i]             = p0;
                    out[tc * 1024 + 2 * i + 1]         = p1;
                    out[12288 + tc * 1024 + 2 * i]     = mu[0];
                    out[12288 + tc * 1024 + 2 * i + 1] = mu[1];
                    out[24576 + tc * 1024 + 2 * i]     = lv[0];
                    out[24576 + tc * 1024 + 2 * i + 1] = lv[1];
                    sh_prev[a] = make_float2(pv0, pv1);
                    sh_pos[a]  = make_float2(pos0, pos1);
                }
            } else {
                pv0 = sh_prev[a].x; pv1 = sh_prev[a].y;
                pos0 = sh_pos[a].x; pos1 = sh_pos[a].y;
            }

            if (t < T_STEPS) {
                // x = [ctx(8), prev(2), c(8), z(2)]
                float x[20];
#pragma unroll
                for (int u = 0; u < 8; u++) x[u] = ctx[u];
                x[8] = pv0; x[9] = pv1;
#pragma unroll
                for (int u = 0; u < 8; u++) x[10 + u] = c[i * 8 + u];
                x[18] = z[2 * i]; x[19] = z[2 * i + 1];

                float xr = 0.f;
                if (lane < 16) {
                    float s = b_in[lane];
#pragma unroll
                    for (int v = 0; v < 20; v++) s += x[v] * W_in[v * 16 + lane];
                    xr = fmaxf(s, 0.f);
                }

                float g = b_ih[lane] + b_hh[lane];
#pragma unroll
                for (int u = 0; u < 16; u++) {
                    float xu = __shfl_sync(0xffffffffu, xr, u);
                    g += xu * W_ih[u * 32 + lane];
                }
#pragma unroll
                for (int u = 0; u < 8; u++) g += h[u] * W_hh[u * 32 + lane];

                int u8 = lane & 7;
                float gi = __shfl_sync(0xffffffffu, g, u8);
                float gf = __shfl_sync(0xffffffffu, g, u8 + 8);
                float gg = __shfl_sync(0xffffffffu, g, u8 + 16);
                float go = __shfl_sync(0xffffffffu, g, u8 + 24);
                float cln = sigf(gf) * cl8 + sigf(gi) * tanhf(gg);
                float hn  = sigf(go) * tanhf(cln);
                if (lane < 8) {
                    sh_cl[a][lane] = cln;
                    sh_h[a][lane]  = hn;
                }
                float hw[8];
#pragma unroll
                for (int u = 0; u < 8; u++) hw[u] = __shfl_sync(0xffffffffu, hn, u);

                // A/B precompute: lane owns d-pair (2l, 2l+1)
                int d = 2 * lane;
                float m0x = sh_Mse0[d],  m0y = sh_Mse0[d + 1];
                float m1x = sh_Mse1[d],  m1y = sh_Mse1[d + 1];
                float bx = pos0 * m0x + pos1 * m1x;
                float by = pos0 * m0y + pos1 * m1y;
                float Ax = sh_b1[d] + bx,     Ay = sh_b1[d + 1] + by;
                float Bx = -bx,               By = -by;
#pragma unroll
                for (int u = 0; u < 8; u++) {
                    float2 wA = *(const float2*)(W1 + (40 + u) * 64 + d);
                    float2 wB = *(const float2*)(W1 + (32 + u) * 64 + d);
                    Ax = fmaf(hw[u], wA.x, Ax); Ay = fmaf(hw[u], wA.y, Ay);
                    Bx = fmaf(hw[u], wB.x, Bx); By = fmaf(hw[u], wB.y, By);
                }
                Ash[a][lane] = make_float2(Ax, Ay);
                g_B2buf[t & 1][lane * N_AG + i] = make_float2(Bx, By);
            }
        }
        if (t == T_STEPS) break;
        __syncthreads();    // Ash/B2 writes done, red consumed

        // ================= grid barrier t =================
        if (tid == 0) {
            __threadfence();
            unsigned v = atomicAdd(&g_cnt[t], 1u);
            if (v == NB - 1) {
                if (t > 0) { g_cnt[t - 1] = 0; g_flag[t - 1] = 0; }
                g_flag[t] = 1;
                __threadfence();
            } else {
                while (g_flag[t] == 0) { }
            }
            __threadfence();
        }
        __syncthreads();

        // ================= pool phase (all 16 warps) =================
        {
            int a = warp >> 2;
            int i = blk * 4 + a;
            int tid128 = (warp & 3) * 32 + lane;
            const float4* B4 = (const float4*)g_B2buf[t & 1];
            const int4 nm = *(const int4*)(nei + ((long)t * N_AG + i) * N_AG + 4 * tid128);

            float acc[4][8];
#pragma unroll
            for (int j = 0; j < 4; j++)
#pragma unroll
                for (int k = 0; k < 8; k++) acc[j][k] = 0.f;

#pragma unroll 8
            for (int dd = 0; dd < 32; dd++) {
                float2 av = Ash[a][dd];
                float4 q0 = B4[dd * 256 + 2 * tid128];
                float4 q1 = B4[dd * 256 + 2 * tid128 + 1];
                float t0x = fmaxf(av.x + q0.x, 0.f), t0y = fmaxf(av.y + q0.y, 0.f);
                float t1x = fmaxf(av.x + q0.z, 0.f), t1y = fmaxf(av.y + q0.w, 0.f);
                float t2x = fmaxf(av.x + q1.x, 0.f), t2y = fmaxf(av.y + q1.y, 0.f);
                float t3x = fmaxf(av.x + q1.z, 0.f), t3y = fmaxf(av.y + q1.w, 0.f);
                float4 wa0 = w2a[dd][0], wa1 = w2a[dd][1];
                float4 wb0 = w2b[dd][0], wb1 = w2b[dd][1];
#define POOL_K(kk, wa_, wb_) \
                acc[0][kk] = fmaf(t0x, wa_, fmaf(t0y, wb_, acc[0][kk])); \
                acc[1][kk] = fmaf(t1x, wa_, fmaf(t1y, wb_, acc[1][kk])); \
                acc[2][kk] = fmaf(t2x, wa_, fmaf(t2y, wb_, acc[2][kk])); \
                acc[3][kk] = fmaf(t3x, wa_, fmaf(t3y, wb_, acc[3][kk]));
                POOL_K(0, wa0.x, wb0.x)
                POOL_K(1, wa0.y, wb0.y)
                POOL_K(2, wa0.z, wb0.z)
                POOL_K(3, wa0.w, wb0.w)
                POOL_K(4, wa1.x, wb1.x)
                POOL_K(5, wa1.y, wb1.y)
                POOL_K(6, wa1.z, wb1.z)
                POOL_K(7, wa1.w, wb1.w)
#undef POOL_K
            }

            float m[8];
            int n0 = nm.x, n1 = nm.y, n2 = nm.z, n3 = nm.w;
#pragma unroll
            for (int k = 0; k < 8; k++) {
                float bk = sh_b2[k];
                float v = 0.f;
                float s0 = fmaxf(acc[0][k] + bk, 0.f);
                float s1 = fmaxf(acc[1][k] + bk, 0.f);
                float s2 = fmaxf(acc[2][k] + bk, 0.f);
                float s3 = fmaxf(acc[3][k] + bk, 0.f);
                if (n0 > 0) v = fmaxf(v, s0);
                if (n1 > 0) v = fmaxf(v, s1);
                if (n2 > 0) v = fmaxf(v, s2);
                if (n3 > 0) v = fmaxf(v, s3);
                v = fmaxf(v, __shfl_xor_sync(0xffffffffu, v, 16));
                v = fmaxf(v, __shfl_xor_sync(0xffffffffu, v, 8));
                v = fmaxf(v, __shfl_xor_sync(0xffffffffu, v, 4));
                v = fmaxf(v, __shfl_xor_sync(0xffffffffu, v, 2));
                v = fmaxf(v, __shfl_xor_sync(0xffffffffu, v, 1));
                m[k] = v;
            }
            if (lane < 8) red[warp][lane] = m[lane];
        }
        __syncthreads();    // red ready for next step; Ash free to overwrite
    }

    // ---------------- replay-safe cleanup of last barrier ----------------
    if (tid == 0) {
        __threadfence();
        unsigned d = atomicAdd(&g_depart, 1u);
        if (d == NB - 1) {
            g_cnt[T_STEPS - 1] = 0;
            g_flag[T_STEPS - 1] = 0;
            g_depart = 0;
            __threadfence();
        }
    }
}

// ------------------------- launch -------------------------
extern "C" void kernel_launch(void* const* d_in, const int* in_sizes, int n_in,
                              void* d_out, int out_size)
{
    const float* p    = (const float*)d_in[0];
    const float* c    = (const float*)d_in[1];
    const float* z    = (const float*)d_in[2];
    const float* obs  = (const float*)d_in[3];
    const float* eps  = (const float*)d_in[4];
    const float* c0   = (const float*)d_in[5];
    const int*   nei  = (const int*)d_in[6];
    const float* W_in = (const float*)d_in[8];
    const float* b_in = (const float*)d_in[9];
    const float* W_ih = (const float*)d_in[10];
    const float* W_hh = (const float*)d_in[11];
    const float* b_ih = (const float*)d_in[12];
    const float* b_hh = (const float*)d_in[13];
    const float* W_m  = (const float*)d_in[14];
    const float* b_m  = (const float*)d_in[15];
    const float* W_v  = (const float*)d_in[16];
    const float* b_v  = (const float*)d_in[17];
    const float* W_zh = (const float*)d_in[18];
    const float* b_zh = (const float*)d_in[19];
    const float* W_se = (const float*)d_in[20];
    const float* b_se = (const float*)d_in[21];
    const float* W1   = (const float*)d_in[22];
    const float* b1   = (const float*)d_in[23];
    const float* W2   = (const float*)d_in[24];
    const float* b2   = (const float*)d_in[25];
    float* out = (float*)d_out;

    k_fused<<<NB, NT>>>(p, c, z, obs, eps, c0, nei,
                        W_in, b_in, W_ih, W_hh, b_ih, b_hh,
                        W_m, b_m, W_v, b_v, W_zh, b_zh,
                        W_se, b_se, W1, b1, W2, b2, out);
}